// round 16
// baseline (speedup 1.0000x reference)
#include <cuda_runtime.h>
#include <cuda_fp16.h>
#include <stdint.h>
#include <string.h>

#define BATCH  512
#define NTOK   1024
#define DDIM   128
#define NCHUNK 8
#define NOUT   1023
#define NTHR   256

// ---------------- smem layout (bytes) ----------------
#define S_A     0             // 32768: A/H1 fp16 [128 rows][256B], XOR swizzle
#define S_W1    32768         // 32768: W1 fp16
#define S_W2    65536         // 16384: W2 fp16
#define S_TOT   81920         // 2048: band totals [4][128] f32
#define S_CCB   83968         // 1024: carry+b1, parity [2][128] f32
#define S_PT    84992         // 2048: epilogue partials, parity [2][2][128] f32
#define S_B2    87040         // 256
#define S_W3    87296         // 256
#define S_B3    87552         // 16
#define SMEM_BYTES 87568

static __device__ __forceinline__ uint32_t smem_u32(const void* p) {
    uint32_t a;
    asm("{ .reg .u64 t; cvta.to.shared.u64 t, %1; cvt.u32.u64 %0, t; }"
        : "=r"(a) : "l"(p));
    return a;
}
static __device__ __forceinline__ uint32_t tswz(uint32_t row, uint32_t cb) {
    return row * 256 + (cb ^ ((row & 7) << 4));
}
static __device__ __forceinline__ uint32_t pack2h(float a, float b) {
    __half2 h = __floats2half2_rn(a, b);
    uint32_t u;
    memcpy(&u, &h, 4);
    return u;
}
static __device__ __forceinline__ float lrelu(float v) {
    return v > 0.f ? v : 0.01f * v;
}
static __device__ __forceinline__ void ldg4(float4& v, const float4* p) {
    asm volatile("ld.global.nc.v4.f32 {%0,%1,%2,%3}, [%4];"
                 : "=f"(v.x), "=f"(v.y), "=f"(v.z), "=f"(v.w) : "l"(p));
}
static __device__ __forceinline__ void ldm4(uint32_t addr, uint32_t& r0, uint32_t& r1,
                                            uint32_t& r2, uint32_t& r3) {
    asm volatile("ldmatrix.sync.aligned.m8n8.x4.shared.b16 {%0,%1,%2,%3}, [%4];"
                 : "=r"(r0), "=r"(r1), "=r"(r2), "=r"(r3) : "r"(addr));
}
static __device__ __forceinline__ void mma16816(float* d, uint32_t a0, uint32_t a1,
                                                uint32_t a2, uint32_t a3,
                                                uint32_t b0, uint32_t b1) {
    asm volatile("mma.sync.aligned.m16n8k16.row.col.f32.f16.f16.f32 "
                 "{%0,%1,%2,%3}, {%4,%5,%6,%7}, {%8,%9}, {%0,%1,%2,%3};"
                 : "+f"(d[0]), "+f"(d[1]), "+f"(d[2]), "+f"(d[3])
                 : "r"(a0), "r"(a1), "r"(a2), "r"(a3), "r"(b0), "r"(b1));
}
static __device__ __forceinline__ void scan_col(float& lo, float& hi, int lane) {
    float o;
    o = __shfl_up_sync(0xffffffffu, lo, 4);  if (lane >= 4)  lo += o;
    o = __shfl_up_sync(0xffffffffu, lo, 8);  if (lane >= 8)  lo += o;
    o = __shfl_up_sync(0xffffffffu, lo, 16); if (lane >= 16) lo += o;
    float tl = __shfl_sync(0xffffffffu, lo, 28 + (lane & 3));
    o = __shfl_up_sync(0xffffffffu, hi, 4);  if (lane >= 4)  hi += o;
    o = __shfl_up_sync(0xffffffffu, hi, 8);  if (lane >= 8)  hi += o;
    o = __shfl_up_sync(0xffffffffu, hi, 16); if (lane >= 16) hi += o;
    hi += tl;
}
// convert one float4 (index idx in [0,4096) over the 128x128 chunk) to fp16 tile
static __device__ __forceinline__ void cvt_store4(float4 v, int idx, char* sm) {
    uint32_t r  = (uint32_t)(idx >> 5);
    uint32_t cb = (uint32_t)((idx & 31) * 8);
    uint32_t a = tswz(r, cb);
    *(uint2*)(sm + S_A + a) = make_uint2(pack2h(v.x, v.y), pack2h(v.z, v.w));
}

__global__ void __launch_bounds__(NTHR, 2)
fused_kernel(const float* __restrict__ x,
             const float* __restrict__ W1, const float* __restrict__ b1,
             const float* __restrict__ W2, const float* __restrict__ b2,
             const float* __restrict__ W3, const float* __restrict__ b3,
             float* __restrict__ out)
{
    extern __shared__ char sm[];
    const uint32_t sb = smem_u32(sm);
    const int tid   = threadIdx.x;
    const int wid   = tid >> 5;
    const int lane  = tid & 31;
    const int quad  = lane >> 2;
    const int four  = lane & 3;
    const int wband = wid >> 1;           // token band: rows wband*32 .. +31 (0..3)
    const int chgrp = wid & 1;            // channel group (0..1), 64 ch each
    const int bb    = blockIdx.x;

    const float* xb = x + (size_t)bb * NTOK * DDIM;

    // ---- prologue: LDG chunk0 -> regs (latency hidden by weight staging) ----
    float4 xv[16];
    {
        const float4* s = (const float4*)xb;
#pragma unroll
        for (int i = 0; i < 16; ++i) ldg4(xv[i], s + tid + i * NTHR);
    }

    // ---- stage weights: fp32 -> fp16 swizzled tiles ----
    {
        const float4* w1 = (const float4*)W1;
#pragma unroll
        for (int i = 0; i < 16; ++i) {
            int idx = tid + i * NTHR;            // [0,4096)
            float4 v = w1[idx];
            uint32_t a = tswz((uint32_t)(idx >> 5), (uint32_t)((idx & 31) * 8));
            *(uint2*)(sm + S_W1 + a) = make_uint2(pack2h(v.x, v.y), pack2h(v.z, v.w));
        }
        const float4* w2 = (const float4*)W2;
#pragma unroll
        for (int i = 0; i < 8; ++i) {
            int idx = tid + i * NTHR;            // [0,2048)
            float4 v = w2[idx];
            uint32_t a = tswz((uint32_t)(idx >> 5), (uint32_t)((idx & 31) * 8));
            *(uint2*)(sm + S_W2 + a) = make_uint2(pack2h(v.x, v.y), pack2h(v.z, v.w));
        }
    }
    if (tid < 128) {
        ((float*)(sm + S_CCB))[tid] = b1[tid];   // CCB[0] = b1 (carry starts 0)
    } else if (tid < 192) {
        ((float*)(sm + S_B2))[tid - 128] = b2[tid - 128];
    } else {
        ((float*)(sm + S_W3))[tid - 192] = W3[tid - 192];
    }
    if (tid == 0) *(float*)(sm + S_B3) = b3[0];

    // ---- convert chunk0 -> A ----
#pragma unroll
    for (int i = 0; i < 16; ++i) cvt_store4(xv[i], tid + i * NTHR, sm);
    __syncthreads();   // A + weights + CCB[0] visible

    // ---- per-lane ldmatrix address pieces ----
    const uint32_t xr   = (uint32_t)((lane & 7) << 4);
    const uint32_t aCol = (uint32_t)(((lane >> 4) & 1) * 16);
    const uint32_t bCol = (uint32_t)(((lane >> 3) & 1) * 16);
    const uint32_t aRowO = (uint32_t)(wband * 32 + (lane & 15)) * 256;   // + t*4096
    const uint32_t bRowO = (uint32_t)((lane & 7) + ((lane >> 4) & 1) * 8) * 256;
    const uint32_t w1B = sb + S_W1 + (uint32_t)(chgrp * 64) * 256 + bRowO;
    const uint32_t w2B = sb + S_W2 + (uint32_t)(chgrp * 32) * 256 + bRowO;
    const uint32_t aB  = sb + S_A + aRowO;

    for (int c = 0; c < NCHUNK; ++c) {
        const int p = c & 1;

        // ---- GEMM1: warp computes [32 tok][64 ch] ----
        float acc[2][8][4];
#pragma unroll
        for (int t = 0; t < 2; ++t)
#pragma unroll
            for (int j = 0; j < 8; ++j) {
                acc[t][j][0] = 0.f; acc[t][j][1] = 0.f;
                acc[t][j][2] = 0.f; acc[t][j][3] = 0.f;
            }
#pragma unroll
        for (int ks = 0; ks < 8; ++ks) {
            uint32_t kc = (uint32_t)(ks * 32);
            uint32_t wk = (bCol | kc) ^ xr;
            uint32_t ak = (aCol | kc) ^ xr;
            uint32_t wh[16];
            ldm4(w1B + wk,         wh[0],  wh[1],  wh[2],  wh[3]);
            ldm4(w1B + 4096 + wk,  wh[4],  wh[5],  wh[6],  wh[7]);
            ldm4(w1B + 8192 + wk,  wh[8],  wh[9],  wh[10], wh[11]);
            ldm4(w1B + 12288 + wk, wh[12], wh[13], wh[14], wh[15]);
#pragma unroll
            for (int t = 0; t < 2; ++t) {
                uint32_t a0, a1, a2, a3;
                ldm4(aB + (uint32_t)(t * 4096) + ak, a0, a1, a2, a3);
#pragma unroll
                for (int j = 0; j < 8; ++j)
                    mma16816(acc[t][j], a0, a1, a2, a3, wh[2 * j], wh[2 * j + 1]);
            }
        }

        // ---- scan over the warp's 32-token band ----
        float ce[8], co[8];
#pragma unroll
        for (int j = 0; j < 8; ++j) { ce[j] = 0.f; co[j] = 0.f; }
#pragma unroll
        for (int t = 0; t < 2; ++t) {
#pragma unroll
            for (int j = 0; j < 8; ++j) {
                scan_col(acc[t][j][0], acc[t][j][2], lane);
                scan_col(acc[t][j][1], acc[t][j][3], lane);
                acc[t][j][0] += ce[j]; acc[t][j][2] += ce[j];
                acc[t][j][1] += co[j]; acc[t][j][3] += co[j];
                ce[j] = __shfl_sync(0xffffffffu, acc[t][j][2], 28 + four);
                co[j] = __shfl_sync(0xffffffffu, acc[t][j][3], 28 + four);
            }
        }
        // band totals -> TOT
        if (quad == 0) {
            float* tp = (float*)(sm + S_TOT) + wband * 128 + chgrp * 64 + 2 * four;
#pragma unroll
            for (int j = 0; j < 8; ++j)
                *(float2*)(tp + j * 8) = make_float2(ce[j], co[j]);
        }
        __syncthreads();                         // B1: TOT visible, GEMM1 reads done

        // ---- per-warp offsets: off = CCB[p] + sum of lower-band totals ----
        float2 offv[8];
        {
            const float2* ccb = (const float2*)(sm + S_CCB + p * 512);
            const float2* tp2 = (const float2*)(sm + S_TOT);
#pragma unroll
            for (int j = 0; j < 8; ++j) {
                int cf = chgrp * 32 + 4 * j + four;
                float2 o = ccb[cf];
                for (int b2i = 0; b2i < wband; ++b2i) {
                    float2 t = tp2[b2i * 64 + cf];
                    o.x += t.x; o.y += t.y;
                }
                offv[j] = o;
            }
        }
        // band-3 warps update CCB for next chunk (2 warps x 2 ch/lane = 128 ch)
        if (wband == 3) {
            const float* ccbC = (const float*)(sm + S_CCB + p * 512);
            float* ccbN = (float*)(sm + S_CCB + (1 - p) * 512);
            const float* tp = (const float*)(sm + S_TOT);
#pragma unroll
            for (int h = 0; h < 2; ++h) {
                int ch = chgrp * 64 + h * 32 + lane;
                ccbN[ch] = ccbC[ch] + tp[ch] + tp[128 + ch] + tp[256 + ch] + tp[384 + ch];
            }
        }

        // ---- apply offsets + leaky, write H1 fp16 (overwrite A tile) ----
        {
            const uint32_t r0 = (uint32_t)(wband * 32 + quad);
#pragma unroll
            for (int t = 0; t < 2; ++t) {
#pragma unroll
                for (int j = 0; j < 8; ++j) {
                    float2 o = offv[j];
                    float v0 = lrelu(acc[t][j][0] + o.x);
                    float v1 = lrelu(acc[t][j][1] + o.y);
                    float v2 = lrelu(acc[t][j][2] + o.x);
                    float v3 = lrelu(acc[t][j][3] + o.y);
                    uint32_t cb = (uint32_t)(chgrp * 128 + j * 16 + 4 * four);
                    uint32_t a0 = tswz(r0 + (uint32_t)(t * 16), cb);
                    *(uint32_t*)(sm + S_A + a0) = pack2h(v0, v1);
                    *(uint32_t*)(sm + S_A + a0 + 8 * 256) = pack2h(v2, v3);
                }
            }
        }
        __syncthreads();                         // B3: H1 + CCB[1-p] visible

        // ---- issue LDG for chunk c+1 (acc dead; latency hides under GEMM2) ----
        if (c + 1 < NCHUNK) {
            const float4* s = (const float4*)(xb + (size_t)(c + 1) * 128 * DDIM);
#pragma unroll
            for (int i = 0; i < 16; ++i) ldg4(xv[i], s + tid + i * NTHR);
        }

        // ---- GEMM2: warp computes [32 tok][32 ch] ----
        float ac2[2][4][4];
#pragma unroll
        for (int t = 0; t < 2; ++t)
#pragma unroll
            for (int j = 0; j < 4; ++j) {
                ac2[t][j][0] = 0.f; ac2[t][j][1] = 0.f;
                ac2[t][j][2] = 0.f; ac2[t][j][3] = 0.f;
            }
#pragma unroll
        for (int ks = 0; ks < 8; ++ks) {
            uint32_t kc = (uint32_t)(ks * 32);
            uint32_t wk = (bCol | kc) ^ xr;
            uint32_t ak = (aCol | kc) ^ xr;
            uint32_t wh[8];
            ldm4(w2B + wk,        wh[0], wh[1], wh[2], wh[3]);
            ldm4(w2B + 4096 + wk, wh[4], wh[5], wh[6], wh[7]);
#pragma unroll
            for (int t = 0; t < 2; ++t) {
                uint32_t a0, a1, a2, a3;
                ldm4(aB + (uint32_t)(t * 4096) + ak, a0, a1, a2, a3);
#pragma unroll
                for (int j = 0; j < 4; ++j)
                    mma16816(ac2[t][j], a0, a1, a2, a3, wh[2 * j], wh[2 * j + 1]);
            }
        }

        // ---- epilogue: partial dot over warp's 32 channels -> PT[p] ----
        {
            const float2* b2p = (const float2*)(sm + S_B2) + chgrp * 16 + four;
            const float2* w3p = (const float2*)(sm + S_W3) + chgrp * 16 + four;
            float* pt = (float*)(sm + S_PT + p * 1024) + chgrp * 128 + wband * 32 + quad;
#pragma unroll
            for (int t = 0; t < 2; ++t) {
                float pl = 0.f, ph = 0.f;
#pragma unroll
                for (int j = 0; j < 4; ++j) {
                    float2 bp = b2p[j * 4];
                    float2 wp = w3p[j * 4];
                    pl += lrelu(ac2[t][j][0] + bp.x) * wp.x
                        + lrelu(ac2[t][j][1] + bp.y) * wp.y;
                    ph += lrelu(ac2[t][j][2] + bp.x) * wp.x
                        + lrelu(ac2[t][j][3] + bp.y) * wp.y;
                }
                pl += __shfl_xor_sync(0xffffffffu, pl, 1);
                pl += __shfl_xor_sync(0xffffffffu, pl, 2);
                ph += __shfl_xor_sync(0xffffffffu, ph, 1);
                ph += __shfl_xor_sync(0xffffffffu, ph, 2);
                if (four == 0) {
                    pt[t * 16] = pl;
                    pt[t * 16 + 8] = ph;
                }
            }
        }
        __syncthreads();                         // B4: PT[p] visible, GEMM2 reads done

        // ---- combine partials + b3 -> out ----
        if (tid < 128) {
            const float* pt = (const float*)(sm + S_PT + p * 1024);
            float s = pt[tid] + pt[128 + tid] + *(const float*)(sm + S_B3);
            int g = c * 128 + tid;
            if (g > 0) out[(size_t)bb * NOUT + g - 1] = s;
        }

        // ---- convert chunk c+1 regs -> A (GEMM2 reads finished at B4) ----
        if (c + 1 < NCHUNK) {
#pragma unroll
            for (int i = 0; i < 16; ++i) cvt_store4(xv[i], tid + i * NTHR, sm);
        }
        __syncthreads();                         // B0: A(c+1) visible; PT reads done
    }
}

// ---------------------------------------------------------------------------
extern "C" void kernel_launch(void* const* d_in, const int* in_sizes, int n_in,
                              void* d_out, int out_size) {
    const float* x  = (const float*)d_in[0];
    const float* W1 = (const float*)d_in[1];
    const float* b1 = (const float*)d_in[2];
    const float* W2 = (const float*)d_in[3];
    const float* b2 = (const float*)d_in[4];
    const float* W3 = (const float*)d_in[5];
    const float* b3 = (const float*)d_in[6];
    float* out = (float*)d_out;

    static bool attr_done = false;
    if (!attr_done) {
        cudaFuncSetAttribute(fused_kernel,
                             cudaFuncAttributeMaxDynamicSharedMemorySize,
                             SMEM_BYTES);
        attr_done = true;
    }

    fused_kernel<<<BATCH, NTHR, SMEM_BYTES>>>(x, W1, b1, W2, b2, W3, b3, out);
}

// round 17
// speedup vs baseline: 1.1165x; 1.1165x over previous
#include <cuda_runtime.h>
#include <cuda_fp16.h>
#include <stdint.h>
#include <string.h>

#define BATCH  512
#define NTOK   1024
#define DDIM   128
#define NOUT   1023
#define NTHR   512
#define HCHUNK 4              // chunks per half-CTA

// ---------------- smem layout (bytes) ----------------
#define S_A0    0             // 32768: A/H1 fp16 [128 rows][256B], XOR swizzle
#define S_A1    32768         // 32768
#define S_W1    65536         // 32768: W1 fp16
#define S_W2    98304         // 16384: W2 fp16
#define S_TOT   114688        // 2048: band totals [4][128] f32
#define S_CCB   116736        // 1024: carry+b1, parity [2][128] f32
#define S_PT    117760        // 4096: epilogue partials, parity [2][4][128] f32
#define S_B2    121856        // 256
#define S_W3    122112        // 256
#define S_B3    122368        // 16
#define SMEM_BYTES 122384

__device__ float g_cc[BATCH * 128];   // Z-carry (incl. b1) after token 511, per batch
__device__ int   g_flag[BATCH];

__global__ void zero_flags() { g_flag[threadIdx.x] = 0; }

static __device__ __forceinline__ uint32_t smem_u32(const void* p) {
    uint32_t a;
    asm("{ .reg .u64 t; cvta.to.shared.u64 t, %1; cvt.u32.u64 %0, t; }"
        : "=r"(a) : "l"(p));
    return a;
}
static __device__ __forceinline__ uint32_t tswz(uint32_t row, uint32_t cb) {
    return row * 256 + (cb ^ ((row & 7) << 4));
}
static __device__ __forceinline__ uint32_t pack2h(float a, float b) {
    __half2 h = __floats2half2_rn(a, b);
    uint32_t u;
    memcpy(&u, &h, 4);
    return u;
}
static __device__ __forceinline__ float lrelu(float v) {
    return v > 0.f ? v : 0.01f * v;
}
static __device__ __forceinline__ void ldg4(float4& v, const float4* p) {
    asm volatile("ld.global.nc.v4.f32 {%0,%1,%2,%3}, [%4];"
                 : "=f"(v.x), "=f"(v.y), "=f"(v.z), "=f"(v.w) : "l"(p));
}
static __device__ __forceinline__ void ldm4(uint32_t addr, uint32_t& r0, uint32_t& r1,
                                            uint32_t& r2, uint32_t& r3) {
    asm volatile("ldmatrix.sync.aligned.m8n8.x4.shared.b16 {%0,%1,%2,%3}, [%4];"
                 : "=r"(r0), "=r"(r1), "=r"(r2), "=r"(r3) : "r"(addr));
}
static __device__ __forceinline__ void mma16816(float* d, uint32_t a0, uint32_t a1,
                                                uint32_t a2, uint32_t a3,
                                                uint32_t b0, uint32_t b1) {
    asm volatile("mma.sync.aligned.m16n8k16.row.col.f32.f16.f16.f32 "
                 "{%0,%1,%2,%3}, {%4,%5,%6,%7}, {%8,%9}, {%0,%1,%2,%3};"
                 : "+f"(d[0]), "+f"(d[1]), "+f"(d[2]), "+f"(d[3])
                 : "r"(a0), "r"(a1), "r"(a2), "r"(a3), "r"(b0), "r"(b1));
}
static __device__ __forceinline__ void scan_col(float& lo, float& hi, int lane) {
    float o;
    o = __shfl_up_sync(0xffffffffu, lo, 4);  if (lane >= 4)  lo += o;
    o = __shfl_up_sync(0xffffffffu, lo, 8);  if (lane >= 8)  lo += o;
    o = __shfl_up_sync(0xffffffffu, lo, 16); if (lane >= 16) lo += o;
    float tl = __shfl_sync(0xffffffffu, lo, 28 + (lane & 3));
    o = __shfl_up_sync(0xffffffffu, hi, 4);  if (lane >= 4)  hi += o;
    o = __shfl_up_sync(0xffffffffu, hi, 8);  if (lane >= 8)  hi += o;
    o = __shfl_up_sync(0xffffffffu, hi, 16); if (lane >= 16) hi += o;
    hi += tl;
}
static __device__ __forceinline__ void cvt_store4(float4 v, int idx, char* sm,
                                                  uint32_t aOff) {
    uint32_t r  = (uint32_t)(idx >> 5);
    uint32_t cb = (uint32_t)((idx & 31) * 8);
    uint32_t a = tswz(r, cb);
    *(uint2*)(sm + aOff + a) = make_uint2(pack2h(v.x, v.y), pack2h(v.z, v.w));
}

__global__ void __launch_bounds__(NTHR, 1)
fused_kernel(const float* __restrict__ x,
             const float* __restrict__ W1, const float* __restrict__ b1,
             const float* __restrict__ W2, const float* __restrict__ b2,
             const float* __restrict__ W3, const float* __restrict__ b3,
             float* __restrict__ out)
{
    extern __shared__ char sm[];
    const uint32_t sb = smem_u32(sm);
    const int tid   = threadIdx.x;
    const int wid   = tid >> 5;
    const int lane  = tid & 31;
    const int quad  = lane >> 2;
    const int four  = lane & 3;
    const int wband = wid >> 2;
    const int chgrp = wid & 3;
    const int half  = (blockIdx.x >= BATCH) ? 1 : 0;   // 0: tokens 0-511, 1: 512-1023
    const int bb    = half ? (blockIdx.x - BATCH) : blockIdx.x;

    const float* xb = x + ((size_t)bb * NTOK + (size_t)half * 512) * DDIM;

    // ---- prologue: LDG chunk0 -> regs (latency hidden by weight staging) ----
    float4 xv[8];
    {
        const float4* s = (const float4*)xb;
#pragma unroll
        for (int i = 0; i < 8; ++i) ldg4(xv[i], s + tid + i * NTHR);
    }

    // ---- stage weights: fp32 -> fp16 swizzled tiles ----
    {
        const float4* w1 = (const float4*)W1;
#pragma unroll
        for (int i = 0; i < 8; ++i) {
            int idx = tid + i * NTHR;
            float4 v = w1[idx];
            uint32_t a = tswz((uint32_t)(idx >> 5), (uint32_t)((idx & 31) * 8));
            *(uint2*)(sm + S_W1 + a) = make_uint2(pack2h(v.x, v.y), pack2h(v.z, v.w));
        }
        const float4* w2 = (const float4*)W2;
#pragma unroll
        for (int i = 0; i < 4; ++i) {
            int idx = tid + i * NTHR;
            float4 v = w2[idx];
            uint32_t a = tswz((uint32_t)(idx >> 5), (uint32_t)((idx & 31) * 8));
            *(uint2*)(sm + S_W2 + a) = make_uint2(pack2h(v.x, v.y), pack2h(v.z, v.w));
        }
    }
    if (tid >= 128 && tid < 192) {
        ((float*)(sm + S_B2))[tid - 128] = b2[tid - 128];
    } else if (tid >= 192 && tid < 256) {
        ((float*)(sm + S_W3))[tid - 192] = W3[tid - 192];
    }
    if (tid == 0) *(float*)(sm + S_B3) = b3[0];

    // ---- convert chunk0 -> A0 ----
#pragma unroll
    for (int i = 0; i < 8; ++i) cvt_store4(xv[i], tid + i * NTHR, sm, S_A0);

    // ---- initial carry: A-half = b1; B-half = handoff from A ----
    if (half == 0) {
        if (tid < 128) ((float*)(sm + S_CCB))[tid] = b1[tid];
    } else {
        if (tid == 0) {
            unsigned v;
            do {
                asm volatile("ld.global.acquire.gpu.u32 %0, [%1];"
                             : "=r"(v) : "l"(g_flag + bb) : "memory");
                if (!v) __nanosleep(200);
            } while (!v);
        }
        __syncthreads();   // flag seen -> g_cc[bb] visible (acquire + block sync)
        if (tid < 128) {
            float v;
            asm volatile("ld.global.cg.f32 %0, [%1];"
                         : "=f"(v) : "l"(g_cc + bb * 128 + tid) : "memory");
            ((float*)(sm + S_CCB))[tid] = v;
        }
    }
    __syncthreads();   // A0 + weights + CCB[0] visible

    // ---- per-lane ldmatrix address pieces ----
    const uint32_t xr   = (uint32_t)((lane & 7) << 4);
    const uint32_t aCol = (uint32_t)(((lane >> 4) & 1) * 16);
    const uint32_t bCol = (uint32_t)(((lane >> 3) & 1) * 16);
    const uint32_t aRowO = (uint32_t)(wband * 32 + (lane & 15)) * 256;
    const uint32_t bRowO = (uint32_t)((lane & 7) + ((lane >> 4) & 1) * 8) * 256;
    const uint32_t w1B = sb + S_W1 + (uint32_t)(chgrp * 32) * 256 + bRowO;
    const uint32_t w2B = sb + S_W2 + (uint32_t)(chgrp * 16) * 256 + bRowO;

    for (int c = 0; c < HCHUNK; ++c) {
        const int p = c & 1;
        const uint32_t aCur = p ? S_A1 : S_A0;
        const uint32_t aNxt = p ? S_A0 : S_A1;
        const uint32_t aB = sb + aCur + aRowO;

        // ---- GEMM1: warp computes [32 tok][32 ch] ----
        float acc[2][4][4];
#pragma unroll
        for (int t = 0; t < 2; ++t)
#pragma unroll
            for (int j = 0; j < 4; ++j) {
                acc[t][j][0] = 0.f; acc[t][j][1] = 0.f;
                acc[t][j][2] = 0.f; acc[t][j][3] = 0.f;
            }
#pragma unroll
        for (int ks = 0; ks < 8; ++ks) {
            uint32_t kc = (uint32_t)(ks * 32);
            uint32_t wk = (bCol | kc) ^ xr;
            uint32_t ak = (aCol | kc) ^ xr;
            uint32_t wh[8];
            ldm4(w1B + wk,        wh[0], wh[1], wh[2], wh[3]);
            ldm4(w1B + 4096 + wk, wh[4], wh[5], wh[6], wh[7]);
#pragma unroll
            for (int t = 0; t < 2; ++t) {
                uint32_t a0, a1, a2, a3;
                ldm4(aB + (uint32_t)(t * 4096) + ak, a0, a1, a2, a3);
#pragma unroll
                for (int j = 0; j < 4; ++j)
                    mma16816(acc[t][j], a0, a1, a2, a3, wh[2 * j], wh[2 * j + 1]);
            }
        }

        // ---- scan over the warp's 32-token band ----
        float ce[4] = {0.f, 0.f, 0.f, 0.f}, co[4] = {0.f, 0.f, 0.f, 0.f};
#pragma unroll
        for (int t = 0; t < 2; ++t) {
#pragma unroll
            for (int j = 0; j < 4; ++j) {
                scan_col(acc[t][j][0], acc[t][j][2], lane);
                scan_col(acc[t][j][1], acc[t][j][3], lane);
                acc[t][j][0] += ce[j]; acc[t][j][2] += ce[j];
                acc[t][j][1] += co[j]; acc[t][j][3] += co[j];
                ce[j] = __shfl_sync(0xffffffffu, acc[t][j][2], 28 + four);
                co[j] = __shfl_sync(0xffffffffu, acc[t][j][3], 28 + four);
            }
        }
        if (quad == 0) {
            float* tp = (float*)(sm + S_TOT) + wband * 128 + chgrp * 32 + 2 * four;
#pragma unroll
            for (int j = 0; j < 4; ++j)
                *(float2*)(tp + j * 8) = make_float2(ce[j], co[j]);
        }
        __syncthreads();                         // B1

        // ---- per-warp offsets: off = CCB[p] + sum of lower-band totals ----
        float2 offv[4];
        {
            const float2* ccb = (const float2*)(sm + S_CCB + p * 512);
            const float2* tp2 = (const float2*)(sm + S_TOT);
#pragma unroll
            for (int j = 0; j < 4; ++j) {
                int cf = chgrp * 16 + 4 * j + four;
                float2 o = ccb[cf];
                for (int b2i = 0; b2i < wband; ++b2i) {
                    float2 t = tp2[b2i * 64 + cf];
                    o.x += t.x; o.y += t.y;
                }
                offv[j] = o;
            }
        }
        if (wband == 3) {
            int ch = chgrp * 32 + lane;
            const float* ccbC = (const float*)(sm + S_CCB + p * 512);
            float* ccbN = (float*)(sm + S_CCB + (1 - p) * 512);
            const float* tp = (const float*)(sm + S_TOT);
            ccbN[ch] = ccbC[ch] + tp[ch] + tp[128 + ch] + tp[256 + ch] + tp[384 + ch];
        }

        // ---- apply offsets + leaky, write H1 fp16 ----
        {
            const uint32_t r0 = (uint32_t)(wband * 32 + quad);
#pragma unroll
            for (int t = 0; t < 2; ++t) {
#pragma unroll
                for (int j = 0; j < 4; ++j) {
                    float2 o = offv[j];
                    float v0 = lrelu(acc[t][j][0] + o.x);
                    float v1 = lrelu(acc[t][j][1] + o.y);
                    float v2 = lrelu(acc[t][j][2] + o.x);
                    float v3 = lrelu(acc[t][j][3] + o.y);
                    uint32_t cb = (uint32_t)(chgrp * 64 + j * 16 + 4 * four);
                    uint32_t a0 = tswz(r0 + (uint32_t)(t * 16), cb);
                    *(uint32_t*)(sm + aCur + a0) = pack2h(v0, v1);
                    *(uint32_t*)(sm + aCur + a0 + 8 * 256) = pack2h(v2, v3);
                }
            }
        }
        __syncthreads();                         // B3

        // ---- issue LDG for chunk c+1 ----
        if (c + 1 < HCHUNK) {
            const float4* s = (const float4*)(xb + (size_t)(c + 1) * 128 * DDIM);
#pragma unroll
            for (int i = 0; i < 8; ++i) ldg4(xv[i], s + tid + i * NTHR);
        }

        // ---- GEMM2: warp computes [32 tok][16 ch] ----
        float ac2[2][2][4];
#pragma unroll
        for (int t = 0; t < 2; ++t)
#pragma unroll
            for (int j = 0; j < 2; ++j) {
                ac2[t][j][0] = 0.f; ac2[t][j][1] = 0.f;
                ac2[t][j][2] = 0.f; ac2[t][j][3] = 0.f;
            }
#pragma unroll
        for (int ks = 0; ks < 8; ++ks) {
            uint32_t kc = (uint32_t)(ks * 32);
            uint32_t wk = (bCol | kc) ^ xr;
            uint32_t ak = (aCol | kc) ^ xr;
            uint32_t wh[4];
            ldm4(w2B + wk, wh[0], wh[1], wh[2], wh[3]);
#pragma unroll
            for (int t = 0; t < 2; ++t) {
                uint32_t a0, a1, a2, a3;
                ldm4(aB + (uint32_t)(t * 4096) + ak, a0, a1, a2, a3);
#pragma unroll
                for (int j = 0; j < 2; ++j)
                    mma16816(ac2[t][j], a0, a1, a2, a3, wh[2 * j], wh[2 * j + 1]);
            }
        }

        // ---- convert chunk c+1 regs -> A_next ----
        if (c + 1 < HCHUNK) {
#pragma unroll
            for (int i = 0; i < 8; ++i) cvt_store4(xv[i], tid + i * NTHR, sm, aNxt);
        }

        // ---- epilogue: partial dot over warp's 16 channels -> PT[p] ----
        {
            const float2* b2p = (const float2*)(sm + S_B2) + chgrp * 8 + four;
            const float2* w3p = (const float2*)(sm + S_W3) + chgrp * 8 + four;
            float2 bp0 = b2p[0], bp1 = b2p[4];
            float2 wp0 = w3p[0], wp1 = w3p[4];
            float* pt = (float*)(sm + S_PT + p * 2048) + chgrp * 128 + wband * 32 + quad;
#pragma unroll
            for (int t = 0; t < 2; ++t) {
                float pl = lrelu(ac2[t][0][0] + bp0.x) * wp0.x
                         + lrelu(ac2[t][0][1] + bp0.y) * wp0.y
                         + lrelu(ac2[t][1][0] + bp1.x) * wp1.x
                         + lrelu(ac2[t][1][1] + bp1.y) * wp1.y;
                float ph = lrelu(ac2[t][0][2] + bp0.x) * wp0.x
                         + lrelu(ac2[t][0][3] + bp0.y) * wp0.y
                         + lrelu(ac2[t][1][2] + bp1.x) * wp1.x
                         + lrelu(ac2[t][1][3] + bp1.y) * wp1.y;
                pl += __shfl_xor_sync(0xffffffffu, pl, 1);
                pl += __shfl_xor_sync(0xffffffffu, pl, 2);
                ph += __shfl_xor_sync(0xffffffffu, ph, 1);
                ph += __shfl_xor_sync(0xffffffffu, ph, 2);
                if (four == 0) {
                    pt[t * 16] = pl;
                    pt[t * 16 + 8] = ph;
                }
            }
        }
        __syncthreads();                         // B4: PT[p] + A_next + CCB visible

        // ---- combine partials + b3 -> out ----
        if (tid < 128) {
            const float* pt = (const float*)(sm + S_PT + p * 2048);
            float s = pt[tid] + pt[128 + tid] + pt[256 + tid] + pt[384 + tid]
                    + *(const float*)(sm + S_B3);
            int g = half * 512 + c * 128 + tid;
            if (g > 0) out[(size_t)bb * NOUT + g - 1] = s;
        }
    }

    // ---- A-half: hand off final carry (CCB[HCHUNK&1=0]) to B-half ----
    if (half == 0) {
        if (tid < 128) {
            float v = ((const float*)(sm + S_CCB))[tid];   // carry incl. b1 after tok 511
            asm volatile("st.global.cg.f32 [%0], %1;"
                         :: "l"(g_cc + bb * 128 + tid), "f"(v) : "memory");
        }
        __threadfence();
        __syncthreads();
        if (tid == 0) atomicExch(g_flag + bb, 1);
    }
}

// ---------------------------------------------------------------------------
extern "C" void kernel_launch(void* const* d_in, const int* in_sizes, int n_in,
                              void* d_out, int out_size) {
    const float* x  = (const float*)d_in[0];
    const float* W1 = (const float*)d_in[1];
    const float* b1 = (const float*)d_in[2];
    const float* W2 = (const float*)d_in[3];
    const float* b2 = (const float*)d_in[4];
    const float* W3 = (const float*)d_in[5];
    const float* b3 = (const float*)d_in[6];
    float* out = (float*)d_out;

    static bool attr_done = false;
    if (!attr_done) {
        cudaFuncSetAttribute(fused_kernel,
                             cudaFuncAttributeMaxDynamicSharedMemorySize,
                             SMEM_BYTES);
        attr_done = true;
    }

    zero_flags<<<1, BATCH>>>();
    fused_kernel<<<2 * BATCH, NTHR, SMEM_BYTES>>>(x, W1, b1, W2, b2, W3, b3, out);
}